// round 10
// baseline (speedup 1.0000x reference)
#include <cuda_runtime.h>
#include <cstdint>

#define NN 50000
#define NE 1600000

typedef unsigned long long u64;

// ---------- scratch (static device globals; no allocation) ----------
__device__ float g_xl[NN * 128];        // [N][H*C]
__device__ float g_uvp[NN * 2 * 192];   // [N][H][u(64)|v(64)|p(64)]
__device__ float g_ex[NE * 2];          // exp(alpha)
__device__ float g_denom[NN * 2];
__device__ float g_Wall[64 * 160];      // [Wcomb_h0 | Wcomb_h1 | Wfold]
__device__ float g_biasAll[160];
__device__ float g_bias192[192];        // [b_att | 0 | 0]

// ---------- f32x2 helpers ----------
__device__ __forceinline__ u64 pack2(float a) {
    u64 d; asm("mov.b64 %0,{%1,%1};" : "=l"(d) : "r"(__float_as_uint(a))); return d;
}
__device__ __forceinline__ u64 ffma2(u64 a, u64 b, u64 c) {
    u64 d; asm("fma.rn.f32x2 %0,%1,%2,%3;" : "=l"(d) : "l"(a), "l"(b), "l"(c)); return d;
}
__device__ __forceinline__ u64 fadd2(u64 a, u64 b) {
    u64 d; asm("add.rn.f32x2 %0,%1,%2;" : "=l"(d) : "l"(a), "l"(b)); return d;
}
__device__ __forceinline__ float2 unpk2(u64 v) {
    float2 r; asm("mov.b64 {%0,%1}, %2;" : "=f"(r.x), "=f"(r.y) : "l"(v)); return r;
}

// ---------- weight folding ----------
// Shapes: We (64, 64), W_att (160, 64), W_eout (64, 32), be (64,), b_att (64,), b_eout (32,)
__global__ void prep_kernel(const float* __restrict__ We, const float* __restrict__ be,
                            const float* __restrict__ W_att, const float* __restrict__ b_att,
                            const float* __restrict__ W_eout, const float* __restrict__ b_eout) {
    int id = blockIdx.x * blockDim.x + threadIdx.x;
    if (id < 64 * 160) {
        int k = id / 160, col = id % 160;
        float acc = 0.f;
        if (col < 128) {                    // attention e-term fold, head h
            int h = col >> 6, j = col & 63;
            #pragma unroll 8
            for (int m = 0; m < 32; m++)
                acc += We[k * 64 + h * 32 + m] * W_att[(128 + m) * 64 + j];
        } else {                            // edge_out fold
            int j = col - 128;
            #pragma unroll 8
            for (int m = 0; m < 64; m++)
                acc += We[k * 64 + m] * W_eout[m * 32 + j];
        }
        g_Wall[id] = acc;
    }
    if (id < 160) {
        float acc = 0.f;
        if (id < 128) {
            int h = id >> 6, j = id & 63;
            for (int m = 0; m < 32; m++)
                acc += be[h * 32 + m] * W_att[(128 + m) * 64 + j];
        } else {
            int j = id - 128;
            for (int m = 0; m < 64; m++)
                acc += be[m] * W_eout[m * 32 + j];
            acc += b_eout[j];
        }
        g_biasAll[id] = acc;
    }
    if (id < 192) g_bias192[id] = (id < 64) ? b_att[id] : 0.f;
}

// ---------- init: node_out = b_nout, denom = 0 ----------
__global__ void init_kernel(float* __restrict__ node_out, const float* __restrict__ b_nout) {
    int i = blockIdx.x * blockDim.x + threadIdx.x;
    if (i < NN * 64) node_out[i] = b_nout[i & 63];
    if (i < NN * 2) g_denom[i] = 0.f;
}

// ---------- xl = x @ Wl + bl : [50000,128] x [128,128], 64-row tiles, 2 rows/thread ----------
__global__ void __launch_bounds__(256, 2)
xl_kernel(const float* __restrict__ x, const float* __restrict__ Wl,
          const float* __restrict__ bl) {
    extern __shared__ float sm[];
    float* sW = sm;             // 16384
    float* sB = sm + 16384;     // 128
    float* sX = sm + 16512;     // 64*132 = 8448
    int tid = threadIdx.x, tx = tid & 7, ty = tid >> 3;
    for (int i = tid; i < 16384; i += 256) sW[i] = Wl[i];
    if (tid < 128) sB[tid] = bl[tid];
    for (int t = blockIdx.x; t < (NN + 63) / 64; t += gridDim.x) {
        int r0 = t * 64;
        __syncthreads();
        for (int i = tid; i < 64 * 32; i += 256) {
            int r = i >> 5, kv = i & 31;
            float4 v = (r0 + r < NN) ? *(const float4*)&x[(size_t)(r0 + r) * 128 + kv * 4]
                                     : make_float4(0.f, 0.f, 0.f, 0.f);
            *(float4*)&sX[r * 132 + kv * 4] = v;
        }
        __syncthreads();
        u64 acc[2][8];
        #pragma unroll
        for (int r = 0; r < 2; r++)
            #pragma unroll
            for (int j = 0; j < 8; j++) acc[r][j] = 0ULL;
        #pragma unroll 2
        for (int k = 0; k < 128; k++) {
            u64 a0 = pack2(sX[(ty * 2 + 0) * 132 + k]);
            u64 a1 = pack2(sX[(ty * 2 + 1) * 132 + k]);
            const ulonglong2* w = (const ulonglong2*)(sW + k * 128);
            #pragma unroll
            for (int j = 0; j < 4; j++) {
                ulonglong2 w2 = w[j * 8 + tx];
                acc[0][2*j] = ffma2(a0, w2.x, acc[0][2*j]); acc[0][2*j+1] = ffma2(a0, w2.y, acc[0][2*j+1]);
                acc[1][2*j] = ffma2(a1, w2.x, acc[1][2*j]); acc[1][2*j+1] = ffma2(a1, w2.y, acc[1][2*j+1]);
            }
        }
        const u64* b2 = (const u64*)sB;
        #pragma unroll
        for (int r = 0; r < 2; r++) {
            int row = r0 + ty * 2 + r;
            if (row < NN) {
                #pragma unroll
                for (int j = 0; j < 4; j++) {
                    u64 vv[2] = { fadd2(acc[r][2*j],   b2[j * 16 + tx * 2]),
                                  fadd2(acc[r][2*j+1], b2[j * 16 + tx * 2 + 1]) };
                    *(float4*)&g_xl[(size_t)row * 128 + j * 32 + tx * 4] = *(float4*)vv;
                }
            }
        }
    }
}

// ---------- [u|v|p](n,h) = xl[n,h] @ [Watt[0:64] | Watt[64:128] | Wnout_h] + [b_att|0|0] ----------
// 64-row tiles, 2 rows/thread, 3 CTAs/SM
__global__ void __launch_bounds__(256, 3)
uvp_kernel(const float* __restrict__ W_att, const float* __restrict__ W_nout) {
    extern __shared__ float sm[];
    float* sW = sm;             // 64*192 = 12288
    float* sB = sm + 12288;     // 192
    float* sX = sm + 12480;     // 64*68 = 4352
    int tid = threadIdx.x, tx = tid & 7, ty = tid >> 3, h = blockIdx.y;
    for (int i = tid; i < 12288; i += 256) {
        int c = i / 192, j = i % 192;
        sW[i] = (j < 128) ? W_att[((j < 64) ? c : 64 + c) * 64 + (j & 63)]
                          : W_nout[(h * 64 + c) * 64 + (j - 128)];
    }
    if (tid < 192) sB[tid] = g_bias192[tid];
    for (int t = blockIdx.x; t < (NN + 63) / 64; t += gridDim.x) {
        int r0 = t * 64;
        __syncthreads();
        for (int i = tid; i < 64 * 16; i += 256) {
            int r = i >> 4, kv = i & 15;
            float4 v = (r0 + r < NN)
                ? *(const float4*)&g_xl[(size_t)(r0 + r) * 128 + h * 64 + kv * 4]
                : make_float4(0.f, 0.f, 0.f, 0.f);
            *(float4*)&sX[r * 68 + kv * 4] = v;
        }
        __syncthreads();
        u64 acc[2][12];
        #pragma unroll
        for (int r = 0; r < 2; r++)
            #pragma unroll
            for (int j = 0; j < 12; j++) acc[r][j] = 0ULL;
        #pragma unroll 2
        for (int k = 0; k < 64; k++) {
            u64 a0 = pack2(sX[(ty * 2 + 0) * 68 + k]);
            u64 a1 = pack2(sX[(ty * 2 + 1) * 68 + k]);
            const ulonglong2* w = (const ulonglong2*)(sW + k * 192);
            #pragma unroll
            for (int j = 0; j < 6; j++) {
                ulonglong2 w2 = w[j * 8 + tx];
                acc[0][2*j] = ffma2(a0, w2.x, acc[0][2*j]); acc[0][2*j+1] = ffma2(a0, w2.y, acc[0][2*j+1]);
                acc[1][2*j] = ffma2(a1, w2.x, acc[1][2*j]); acc[1][2*j+1] = ffma2(a1, w2.y, acc[1][2*j+1]);
            }
        }
        const u64* b2 = (const u64*)sB;
        #pragma unroll
        for (int r = 0; r < 2; r++) {
            int n = r0 + ty * 2 + r;
            if (n < NN) {
                #pragma unroll
                for (int j = 0; j < 6; j++) {
                    u64 vv[2] = { fadd2(acc[r][2*j],   b2[j * 16 + tx * 2]),
                                  fadd2(acc[r][2*j+1], b2[j * 16 + tx * 2 + 1]) };
                    *(float4*)&g_uvp[((size_t)n * 2 + h) * 192 + j * 32 + tx * 4] = *(float4*)vv;
                }
            }
        }
    }
}

// ---------- edge: z = ea@Wall + bias (registers); edge_out; alpha via shuffle; denom ----------
// 64-edge tiles, 2 edges/thread, 3 CTAs/SM
__global__ void __launch_bounds__(256, 3)
edge_kernel(const float* __restrict__ ea, const int* __restrict__ ei,
            const float* __restrict__ att, float* __restrict__ eout) {
    extern __shared__ float sm[];
    float* sW  = sm;             // 64*160 = 10240
    float* sB  = sm + 10240;     // 160
    float* sA  = sm + 10400;     // 128
    float* sEA = sm + 10528;     // 64*68 = 4352
    int*   sSD = (int*)(sm + 14880); // 128: [src(64) | dst(64)]
    int tid = threadIdx.x, tx = tid & 7, ty = tid >> 3;
    for (int i = tid; i < 10240; i += 256) sW[i] = g_Wall[i];
    if (tid < 160) sB[tid] = g_biasAll[tid];
    if (tid < 128) sA[tid] = att[tid];
    for (int t = blockIdx.x; t < NE / 64; t += gridDim.x) {
        int e0 = t * 64;
        __syncthreads();        // protect sEA/sSD from previous iteration's readers
        for (int i = tid; i < 64 * 16; i += 256) {
            int r = i >> 4, kv = i & 15;
            *(float4*)&sEA[r * 68 + kv * 4] =
                *(const float4*)&ea[(size_t)(e0 + r) * 64 + kv * 4];
        }
        if (tid < 64) sSD[tid] = ei[e0 + tid];
        else if (tid < 128) sSD[tid] = ei[NE + e0 + tid - 64];
        __syncthreads();
        u64 acc[2][10];
        #pragma unroll
        for (int r = 0; r < 2; r++)
            #pragma unroll
            for (int j = 0; j < 10; j++) acc[r][j] = 0ULL;
        #pragma unroll 2
        for (int k = 0; k < 64; k++) {
            u64 a0 = pack2(sEA[(ty * 2 + 0) * 68 + k]);
            u64 a1 = pack2(sEA[(ty * 2 + 1) * 68 + k]);
            const ulonglong2* w = (const ulonglong2*)(sW + k * 160);
            #pragma unroll
            for (int j = 0; j < 5; j++) {
                ulonglong2 w2 = w[j * 8 + tx];
                acc[0][2*j] = ffma2(a0, w2.x, acc[0][2*j]); acc[0][2*j+1] = ffma2(a0, w2.y, acc[0][2*j+1]);
                acc[1][2*j] = ffma2(a1, w2.x, acc[1][2*j]); acc[1][2*j+1] = ffma2(a1, w2.y, acc[1][2*j+1]);
            }
        }
        const u64* b2 = (const u64*)sB;
        #pragma unroll
        for (int r = 0; r < 2; r++) {
            int e = ty * 2 + r, ge = e0 + e;
            int src = sSD[e], dst = sSD[64 + e];
            // edge_out cols (j=4), bias folded
            {
                u64 vv[2] = { fadd2(acc[r][8], b2[4 * 16 + tx * 2]),
                              fadd2(acc[r][9], b2[4 * 16 + tx * 2 + 1]) };
                *(float4*)&eout[(size_t)ge * 32 + tx * 4] = *(float4*)vv;
            }
            // alpha partials over this thread's 8 cols per head
            float p0 = 0.f, p1 = 0.f;
            #pragma unroll
            for (int hh = 0; hh < 2; hh++) {
                const float* gu = &g_uvp[((size_t)dst * 2 + hh) * 192];
                const float* gv = &g_uvp[((size_t)src * 2 + hh) * 192 + 64];
                float p = 0.f;
                #pragma unroll
                for (int jj = 0; jj < 2; jj++) {
                    int j = hh * 2 + jj;
                    int lc = jj * 32 + tx * 4;
                    float2 zA = unpk2(fadd2(acc[r][2*j],   b2[j * 16 + tx * 2]));
                    float2 zB = unpk2(fadd2(acc[r][2*j+1], b2[j * 16 + tx * 2 + 1]));
                    float4 uu = *(const float4*)&gu[lc];
                    float4 vv = *(const float4*)&gv[lc];
                    float4 aa = *(const float4*)&sA[hh * 64 + lc];
                    float t0;
                    t0 = uu.x + vv.x + zA.x; t0 = t0 > 0.f ? t0 : 0.2f * t0; p = fmaf(t0, aa.x, p);
                    t0 = uu.y + vv.y + zA.y; t0 = t0 > 0.f ? t0 : 0.2f * t0; p = fmaf(t0, aa.y, p);
                    t0 = uu.z + vv.z + zB.x; t0 = t0 > 0.f ? t0 : 0.2f * t0; p = fmaf(t0, aa.z, p);
                    t0 = uu.w + vv.w + zB.y; t0 = t0 > 0.f ? t0 : 0.2f * t0; p = fmaf(t0, aa.w, p);
                }
                if (hh == 0) p0 = p; else p1 = p;
            }
            // reduce across the 8 tx lanes (lane bits 0-2)
            #pragma unroll
            for (int off = 1; off < 8; off <<= 1) {
                p0 += __shfl_xor_sync(0xFFFFFFFFu, p0, off);
                p1 += __shfl_xor_sync(0xFFFFFFFFu, p1, off);
            }
            if (tx == 0) {
                float ex = __expf(p0);   // softmax shift-invariant; |alpha| small
                g_ex[(size_t)ge * 2] = ex;
                atomicAdd(&g_denom[dst * 2], ex);
            } else if (tx == 1) {
                float ex = __expf(p1);
                g_ex[(size_t)ge * 2 + 1] = ex;
                atomicAdd(&g_denom[dst * 2 + 1], ex);
            }
        }
    }
}

// ---------- node_out[dst] += sum_h (ex_h/denom_h) * p[src,h] ----------
__global__ void scatter_kernel(const int* __restrict__ ei, float* __restrict__ node_out) {
    int gid = blockIdx.x * blockDim.x + threadIdx.x;
    if (gid >= NE * 8) return;
    int e = gid >> 3, part = gid & 7;
    int src = ei[e];
    int dst = ei[NE + e];
    float w0 = g_ex[(size_t)e * 2]     / (g_denom[dst * 2]     + 1e-16f);
    float w1 = g_ex[(size_t)e * 2 + 1] / (g_denom[dst * 2 + 1] + 1e-16f);
    const float4* p0 = (const float4*)&g_uvp[((size_t)src * 2 + 0) * 192 + 128];
    const float4* p1 = (const float4*)&g_uvp[((size_t)src * 2 + 1) * 192 + 128];
    float* ob = node_out + (size_t)dst * 64 + part * 8;
    #pragma unroll
    for (int i = 0; i < 2; i++) {
        float4 a = p0[part * 2 + i];
        float4 b = p1[part * 2 + i];
        float4 s;
        s.x = w0 * a.x + w1 * b.x;
        s.y = w0 * a.y + w1 * b.y;
        s.z = w0 * a.z + w1 * b.z;
        s.w = w0 * a.w + w1 * b.w;
        asm volatile("red.global.add.v4.f32 [%0], {%1,%2,%3,%4};"
                     :: "l"(ob + i * 4), "f"(s.x), "f"(s.y), "f"(s.z), "f"(s.w)
                     : "memory");
    }
}

// ---------- launch ----------
extern "C" void kernel_launch(void* const* d_in, const int* in_sizes, int n_in,
                              void* d_out, int out_size) {
    (void)in_sizes; (void)n_in; (void)out_size;
    const float* x          = (const float*)d_in[0];
    const float* edge_attr  = (const float*)d_in[1];
    const int*   edge_index = (const int*)d_in[2];
    const float* Wl     = (const float*)d_in[3];
    const float* bl     = (const float*)d_in[4];
    const float* We     = (const float*)d_in[5];
    const float* be     = (const float*)d_in[6];
    const float* W_att  = (const float*)d_in[7];
    const float* b_att  = (const float*)d_in[8];
    const float* att    = (const float*)d_in[9];
    const float* W_nout = (const float*)d_in[10];
    const float* b_nout = (const float*)d_in[11];
    const float* W_eout = (const float*)d_in[12];
    const float* b_eout = (const float*)d_in[13];

    float* node_out = (float*)d_out;                   // [50000, 64]
    float* edge_out = node_out + (size_t)NN * 64;      // [1600000, 32]

    const int smXL   = (16384 + 128 + 64 * 132) * 4;   //  99840 -> 2 CTAs/SM
    const int smUVP  = (12288 + 192 + 64 * 68) * 4;    //  67328 -> 3 CTAs/SM
    const int smEDGE = (10528 + 64 * 68) * 4 + 128 * 4; //  60032 -> 3 CTAs/SM
    cudaFuncSetAttribute(xl_kernel,   cudaFuncAttributeMaxDynamicSharedMemorySize, smXL);
    cudaFuncSetAttribute(uvp_kernel,  cudaFuncAttributeMaxDynamicSharedMemorySize, smUVP);
    cudaFuncSetAttribute(edge_kernel, cudaFuncAttributeMaxDynamicSharedMemorySize, smEDGE);

    prep_kernel<<<40, 256>>>(We, be, W_att, b_att, W_eout, b_eout);
    init_kernel<<<(NN * 64 + 255) / 256, 256>>>(node_out, b_nout);
    xl_kernel<<<296, 256, smXL>>>(x, Wl, bl);
    uvp_kernel<<<dim3(444, 2), 256, smUVP>>>(W_att, W_nout);
    edge_kernel<<<444, 256, smEDGE>>>(edge_attr, edge_index, att, edge_out);
    scatter_kernel<<<(NE * 8 + 255) / 256, 256>>>(edge_index, node_out);
}

// round 11
// speedup vs baseline: 1.0902x; 1.0902x over previous
#include <cuda_runtime.h>
#include <cstdint>

#define NN 50000
#define NE 1600000

typedef unsigned long long u64;

// ---------- scratch (static device globals; no allocation) ----------
__device__ float g_xl[NN * 128];        // [N][H*C]
__device__ float g_uvp[NN * 2 * 192];   // [N][H][u(64)|v(64)|p(64)]
__device__ float g_accH[NN * 128];      // [N][H][64] unnormalized sum ex_h * p[src,h]
__device__ float g_denom[NN * 2];
__device__ float g_Wall[64 * 160];      // [Wcomb_h0 | Wcomb_h1 | Wfold]
__device__ float g_biasAll[160];
__device__ float g_bias192[192];        // [b_att | 0 | 0]

// ---------- f32x2 helpers ----------
__device__ __forceinline__ u64 pack2(float a) {
    u64 d; asm("mov.b64 %0,{%1,%1};" : "=l"(d) : "r"(__float_as_uint(a))); return d;
}
__device__ __forceinline__ u64 ffma2(u64 a, u64 b, u64 c) {
    u64 d; asm("fma.rn.f32x2 %0,%1,%2,%3;" : "=l"(d) : "l"(a), "l"(b), "l"(c)); return d;
}
__device__ __forceinline__ u64 fadd2(u64 a, u64 b) {
    u64 d; asm("add.rn.f32x2 %0,%1,%2;" : "=l"(d) : "l"(a), "l"(b)); return d;
}
__device__ __forceinline__ float2 unpk2(u64 v) {
    float2 r; asm("mov.b64 {%0,%1}, %2;" : "=f"(r.x), "=f"(r.y) : "l"(v)); return r;
}

// ---------- weight folding ----------
// Shapes: We (64, 64), W_att (160, 64), W_eout (64, 32), be (64,), b_att (64,), b_eout (32,)
__global__ void prep_kernel(const float* __restrict__ We, const float* __restrict__ be,
                            const float* __restrict__ W_att, const float* __restrict__ b_att,
                            const float* __restrict__ W_eout, const float* __restrict__ b_eout) {
    int id = blockIdx.x * blockDim.x + threadIdx.x;
    if (id < 64 * 160) {
        int k = id / 160, col = id % 160;
        float acc = 0.f;
        if (col < 128) {                    // attention e-term fold, head h
            int h = col >> 6, j = col & 63;
            #pragma unroll 8
            for (int m = 0; m < 32; m++)
                acc += We[k * 64 + h * 32 + m] * W_att[(128 + m) * 64 + j];
        } else {                            // edge_out fold
            int j = col - 128;
            #pragma unroll 8
            for (int m = 0; m < 64; m++)
                acc += We[k * 64 + m] * W_eout[m * 32 + j];
        }
        g_Wall[id] = acc;
    }
    if (id < 160) {
        float acc = 0.f;
        if (id < 128) {
            int h = id >> 6, j = id & 63;
            for (int m = 0; m < 32; m++)
                acc += be[h * 32 + m] * W_att[(128 + m) * 64 + j];
        } else {
            int j = id - 128;
            for (int m = 0; m < 64; m++)
                acc += be[m] * W_eout[m * 32 + j];
            acc += b_eout[j];
        }
        g_biasAll[id] = acc;
    }
    if (id < 192) g_bias192[id] = (id < 64) ? b_att[id] : 0.f;
}

// ---------- init: accH = 0, denom = 0 ----------
__global__ void init_kernel() {
    int i = blockIdx.x * blockDim.x + threadIdx.x;
    if (i < NN * 128) g_accH[i] = 0.f;
    if (i < NN * 2) g_denom[i] = 0.f;
}

// ---------- xl = x @ Wl + bl : [50000,128] x [128,128], 128-row tiles, 4 rows/thread ----------
__global__ void __launch_bounds__(256, 1)
xl_kernel(const float* __restrict__ x, const float* __restrict__ Wl,
          const float* __restrict__ bl) {
    extern __shared__ float sm[];
    float* sW = sm;             // 16384
    float* sB = sm + 16384;     // 128
    float* sX = sm + 16512;     // 128*132
    int tid = threadIdx.x, tx = tid & 7, ty = tid >> 3;
    for (int i = tid; i < 16384; i += 256) sW[i] = Wl[i];
    if (tid < 128) sB[tid] = bl[tid];
    for (int t = blockIdx.x; t < (NN + 127) / 128; t += gridDim.x) {
        int r0 = t * 128;
        __syncthreads();
        for (int i = tid; i < 128 * 32; i += 256) {
            int r = i >> 5, kv = i & 31;
            float4 v = (r0 + r < NN) ? *(const float4*)&x[(size_t)(r0 + r) * 128 + kv * 4]
                                     : make_float4(0.f, 0.f, 0.f, 0.f);
            *(float4*)&sX[r * 132 + kv * 4] = v;
        }
        __syncthreads();
        u64 acc[4][8];
        #pragma unroll
        for (int r = 0; r < 4; r++)
            #pragma unroll
            for (int j = 0; j < 8; j++) acc[r][j] = 0ULL;
        #pragma unroll 2
        for (int k = 0; k < 128; k++) {
            u64 a0 = pack2(sX[(ty * 4 + 0) * 132 + k]);
            u64 a1 = pack2(sX[(ty * 4 + 1) * 132 + k]);
            u64 a2 = pack2(sX[(ty * 4 + 2) * 132 + k]);
            u64 a3 = pack2(sX[(ty * 4 + 3) * 132 + k]);
            const ulonglong2* w = (const ulonglong2*)(sW + k * 128);
            #pragma unroll
            for (int j = 0; j < 4; j++) {
                ulonglong2 w2 = w[j * 8 + tx];
                acc[0][2*j] = ffma2(a0, w2.x, acc[0][2*j]); acc[0][2*j+1] = ffma2(a0, w2.y, acc[0][2*j+1]);
                acc[1][2*j] = ffma2(a1, w2.x, acc[1][2*j]); acc[1][2*j+1] = ffma2(a1, w2.y, acc[1][2*j+1]);
                acc[2][2*j] = ffma2(a2, w2.x, acc[2][2*j]); acc[2][2*j+1] = ffma2(a2, w2.y, acc[2][2*j+1]);
                acc[3][2*j] = ffma2(a3, w2.x, acc[3][2*j]); acc[3][2*j+1] = ffma2(a3, w2.y, acc[3][2*j+1]);
            }
        }
        const u64* b2 = (const u64*)sB;
        #pragma unroll
        for (int r = 0; r < 4; r++) {
            int row = r0 + ty * 4 + r;
            if (row < NN) {
                #pragma unroll
                for (int j = 0; j < 4; j++) {
                    u64 vv[2] = { fadd2(acc[r][2*j],   b2[j * 16 + tx * 2]),
                                  fadd2(acc[r][2*j+1], b2[j * 16 + tx * 2 + 1]) };
                    *(float4*)&g_xl[(size_t)row * 128 + j * 32 + tx * 4] = *(float4*)vv;
                }
            }
        }
    }
}

// ---------- [u|v|p](n,h) = xl[n,h] @ [Watt[0:64] | Watt[64:128] | Wnout_h] + [b_att|0|0] ----------
// 96-row tiles, 3 rows/thread, 2 CTAs/SM (no spill: acc 72 regs < 128 cap)
__global__ void __launch_bounds__(256, 2)
uvp_kernel(const float* __restrict__ W_att, const float* __restrict__ W_nout) {
    extern __shared__ float sm[];
    float* sW = sm;             // 64*192 = 12288
    float* sB = sm + 12288;     // 192
    float* sX = sm + 12480;     // 96*68 = 6528
    int tid = threadIdx.x, tx = tid & 7, ty = tid >> 3, h = blockIdx.y;
    for (int i = tid; i < 12288; i += 256) {
        int c = i / 192, j = i % 192;
        sW[i] = (j < 128) ? W_att[((j < 64) ? c : 64 + c) * 64 + (j & 63)]
                          : W_nout[(h * 64 + c) * 64 + (j - 128)];
    }
    if (tid < 192) sB[tid] = g_bias192[tid];
    for (int t = blockIdx.x; t < (NN + 95) / 96; t += gridDim.x) {
        int r0 = t * 96;
        __syncthreads();
        for (int i = tid; i < 96 * 16; i += 256) {
            int r = i >> 4, kv = i & 15;
            float4 v = (r0 + r < NN)
                ? *(const float4*)&g_xl[(size_t)(r0 + r) * 128 + h * 64 + kv * 4]
                : make_float4(0.f, 0.f, 0.f, 0.f);
            *(float4*)&sX[r * 68 + kv * 4] = v;
        }
        __syncthreads();
        u64 acc[3][12];
        #pragma unroll
        for (int r = 0; r < 3; r++)
            #pragma unroll
            for (int j = 0; j < 12; j++) acc[r][j] = 0ULL;
        #pragma unroll 2
        for (int k = 0; k < 64; k++) {
            u64 a0 = pack2(sX[(ty * 3 + 0) * 68 + k]);
            u64 a1 = pack2(sX[(ty * 3 + 1) * 68 + k]);
            u64 a2 = pack2(sX[(ty * 3 + 2) * 68 + k]);
            const ulonglong2* w = (const ulonglong2*)(sW + k * 192);
            #pragma unroll
            for (int j = 0; j < 6; j++) {
                ulonglong2 w2 = w[j * 8 + tx];
                acc[0][2*j] = ffma2(a0, w2.x, acc[0][2*j]); acc[0][2*j+1] = ffma2(a0, w2.y, acc[0][2*j+1]);
                acc[1][2*j] = ffma2(a1, w2.x, acc[1][2*j]); acc[1][2*j+1] = ffma2(a1, w2.y, acc[1][2*j+1]);
                acc[2][2*j] = ffma2(a2, w2.x, acc[2][2*j]); acc[2][2*j+1] = ffma2(a2, w2.y, acc[2][2*j+1]);
            }
        }
        const u64* b2 = (const u64*)sB;
        #pragma unroll
        for (int r = 0; r < 3; r++) {
            int n = r0 + ty * 3 + r;
            if (n < NN) {
                #pragma unroll
                for (int j = 0; j < 6; j++) {
                    u64 vv[2] = { fadd2(acc[r][2*j],   b2[j * 16 + tx * 2]),
                                  fadd2(acc[r][2*j+1], b2[j * 16 + tx * 2 + 1]) };
                    *(float4*)&g_uvp[((size_t)n * 2 + h) * 192 + j * 32 + tx * 4] = *(float4*)vv;
                }
            }
        }
    }
}

// ---------- edge: z = ea@Wall + bias (regs); edge_out; alpha via shuffle; denom; fused scatter ----------
// 128-edge tiles, 4 edges/thread, 2 CTAs/SM (R8 config + fused scatter)
__global__ void __launch_bounds__(256, 2)
edge_kernel(const float* __restrict__ ea, const int* __restrict__ ei,
            const float* __restrict__ att, float* __restrict__ eout) {
    extern __shared__ float sm[];
    float* sW  = sm;             // 64*160 = 10240
    float* sB  = sm + 10240;     // 160
    float* sA  = sm + 10400;     // 128
    float* sEA = sm + 10528;     // 128*68 = 8704
    int*   sSD = (int*)(sm + 19232); // 256: [src(128) | dst(128)]
    int tid = threadIdx.x, tx = tid & 7, ty = tid >> 3;
    for (int i = tid; i < 10240; i += 256) sW[i] = g_Wall[i];
    if (tid < 160) sB[tid] = g_biasAll[tid];
    if (tid < 128) sA[tid] = att[tid];
    for (int t = blockIdx.x; t < NE / 128; t += gridDim.x) {
        int e0 = t * 128;
        __syncthreads();        // protect sEA/sSD from previous iteration's readers
        for (int i = tid; i < 128 * 16; i += 256) {
            int r = i >> 4, kv = i & 15;
            *(float4*)&sEA[r * 68 + kv * 4] =
                *(const float4*)&ea[(size_t)(e0 + r) * 64 + kv * 4];
        }
        if (tid < 128) sSD[tid] = ei[e0 + tid];
        else           sSD[tid] = ei[NE + e0 + tid - 128];
        __syncthreads();
        u64 acc[4][10];
        #pragma unroll
        for (int r = 0; r < 4; r++)
            #pragma unroll
            for (int j = 0; j < 10; j++) acc[r][j] = 0ULL;
        #pragma unroll 2
        for (int k = 0; k < 64; k++) {
            u64 a0 = pack2(sEA[(ty * 4 + 0) * 68 + k]);
            u64 a1 = pack2(sEA[(ty * 4 + 1) * 68 + k]);
            u64 a2 = pack2(sEA[(ty * 4 + 2) * 68 + k]);
            u64 a3 = pack2(sEA[(ty * 4 + 3) * 68 + k]);
            const ulonglong2* w = (const ulonglong2*)(sW + k * 160);
            #pragma unroll
            for (int j = 0; j < 5; j++) {
                ulonglong2 w2 = w[j * 8 + tx];
                acc[0][2*j] = ffma2(a0, w2.x, acc[0][2*j]); acc[0][2*j+1] = ffma2(a0, w2.y, acc[0][2*j+1]);
                acc[1][2*j] = ffma2(a1, w2.x, acc[1][2*j]); acc[1][2*j+1] = ffma2(a1, w2.y, acc[1][2*j+1]);
                acc[2][2*j] = ffma2(a2, w2.x, acc[2][2*j]); acc[2][2*j+1] = ffma2(a2, w2.y, acc[2][2*j+1]);
                acc[3][2*j] = ffma2(a3, w2.x, acc[3][2*j]); acc[3][2*j+1] = ffma2(a3, w2.y, acc[3][2*j+1]);
            }
        }
        const u64* b2 = (const u64*)sB;
        #pragma unroll
        for (int r = 0; r < 4; r++) {
            int e = ty * 4 + r, ge = e0 + e;
            int src = sSD[e], dst = sSD[128 + e];
            // edge_out cols (j=4), bias folded
            {
                u64 vv[2] = { fadd2(acc[r][8], b2[4 * 16 + tx * 2]),
                              fadd2(acc[r][9], b2[4 * 16 + tx * 2 + 1]) };
                *(float4*)&eout[(size_t)ge * 32 + tx * 4] = *(float4*)vv;
            }
            // alpha partials over this thread's 8 cols per head
            float p0 = 0.f, p1 = 0.f;
            #pragma unroll
            for (int hh = 0; hh < 2; hh++) {
                const float* gu = &g_uvp[((size_t)dst * 2 + hh) * 192];
                const float* gv = &g_uvp[((size_t)src * 2 + hh) * 192 + 64];
                float p = 0.f;
                #pragma unroll
                for (int jj = 0; jj < 2; jj++) {
                    int j = hh * 2 + jj;
                    int lc = jj * 32 + tx * 4;
                    float2 zA = unpk2(fadd2(acc[r][2*j],   b2[j * 16 + tx * 2]));
                    float2 zB = unpk2(fadd2(acc[r][2*j+1], b2[j * 16 + tx * 2 + 1]));
                    float4 uu = *(const float4*)&gu[lc];
                    float4 vv = *(const float4*)&gv[lc];
                    float4 aa = *(const float4*)&sA[hh * 64 + lc];
                    float t0;
                    t0 = uu.x + vv.x + zA.x; t0 = t0 > 0.f ? t0 : 0.2f * t0; p = fmaf(t0, aa.x, p);
                    t0 = uu.y + vv.y + zA.y; t0 = t0 > 0.f ? t0 : 0.2f * t0; p = fmaf(t0, aa.y, p);
                    t0 = uu.z + vv.z + zB.x; t0 = t0 > 0.f ? t0 : 0.2f * t0; p = fmaf(t0, aa.z, p);
                    t0 = uu.w + vv.w + zB.y; t0 = t0 > 0.f ? t0 : 0.2f * t0; p = fmaf(t0, aa.w, p);
                }
                if (hh == 0) p0 = p; else p1 = p;
            }
            // reduce across the 8 tx lanes -> all lanes hold full alpha sums
            #pragma unroll
            for (int off = 1; off < 8; off <<= 1) {
                p0 += __shfl_xor_sync(0xFFFFFFFFu, p0, off);
                p1 += __shfl_xor_sync(0xFFFFFFFFu, p1, off);
            }
            float ex0 = __expf(p0);   // softmax shift-invariant; |alpha| small
            float ex1 = __expf(p1);
            if (tx == 0) atomicAdd(&g_denom[dst * 2], ex0);
            else if (tx == 1) atomicAdd(&g_denom[dst * 2 + 1], ex1);
            // fused scatter: accH[dst,h] += ex_h * p[src,h]  (8 lanes x 8 cols)
            const float4* pa = (const float4*)&g_uvp[((size_t)src * 2 + 0) * 192 + 128 + tx * 8];
            const float4* pb = (const float4*)&g_uvp[((size_t)src * 2 + 1) * 192 + 128 + tx * 8];
            float* oa = &g_accH[(size_t)dst * 128 + tx * 8];
            float* ob = &g_accH[(size_t)dst * 128 + 64 + tx * 8];
            #pragma unroll
            for (int i = 0; i < 2; i++) {
                float4 a = pa[i];
                asm volatile("red.global.add.v4.f32 [%0], {%1,%2,%3,%4};"
                             :: "l"(oa + i * 4), "f"(ex0 * a.x), "f"(ex0 * a.y),
                                "f"(ex0 * a.z), "f"(ex0 * a.w) : "memory");
                float4 b = pb[i];
                asm volatile("red.global.add.v4.f32 [%0], {%1,%2,%3,%4};"
                             :: "l"(ob + i * 4), "f"(ex1 * b.x), "f"(ex1 * b.y),
                                "f"(ex1 * b.z), "f"(ex1 * b.w) : "memory");
            }
        }
    }
}

// ---------- normalize: node_out = b_nout + accH0/denom0 + accH1/denom1 ----------
__global__ void normalize_kernel(float* __restrict__ node_out, const float* __restrict__ b_nout) {
    int i = blockIdx.x * blockDim.x + threadIdx.x;
    if (i >= NN * 16) return;
    int n = i >> 4, q = i & 15;
    float d0 = g_denom[n * 2]     + 1e-16f;
    float d1 = g_denom[n * 2 + 1] + 1e-16f;
    float4 a0 = *(const float4*)&g_accH[(size_t)n * 128 + q * 4];
    float4 a1 = *(const float4*)&g_accH[(size_t)n * 128 + 64 + q * 4];
    float4 bb = *(const float4*)&b_nout[q * 4];
    float4 o;
    o.x = bb.x + a0.x / d0 + a1.x / d1;
    o.y = bb.y + a0.y / d0 + a1.y / d1;
    o.z = bb.z + a0.z / d0 + a1.z / d1;
    o.w = bb.w + a0.w / d0 + a1.w / d1;
    *(float4*)&node_out[(size_t)n * 64 + q * 4] = o;
}

// ---------- launch ----------
extern "C" void kernel_launch(void* const* d_in, const int* in_sizes, int n_in,
                              void* d_out, int out_size) {
    (void)in_sizes; (void)n_in; (void)out_size;
    const float* x          = (const float*)d_in[0];
    const float* edge_attr  = (const float*)d_in[1];
    const int*   edge_index = (const int*)d_in[2];
    const float* Wl     = (const float*)d_in[3];
    const float* bl     = (const float*)d_in[4];
    const float* We     = (const float*)d_in[5];
    const float* be     = (const float*)d_in[6];
    const float* W_att  = (const float*)d_in[7];
    const float* b_att  = (const float*)d_in[8];
    const float* att    = (const float*)d_in[9];
    const float* W_nout = (const float*)d_in[10];
    const float* b_nout = (const float*)d_in[11];
    const float* W_eout = (const float*)d_in[12];
    const float* b_eout = (const float*)d_in[13];

    float* node_out = (float*)d_out;                   // [50000, 64]
    float* edge_out = node_out + (size_t)NN * 64;      // [1600000, 32]

    const int smXL   = (16384 + 128 + 128 * 132) * 4;      // 133632 -> 1 CTA/SM
    const int smUVP  = (12288 + 192 + 96 * 68) * 4;        //  76032 -> 2 CTAs/SM
    const int smEDGE = (10528 + 128 * 68) * 4 + 256 * 4;   //  77952 -> 2 CTAs/SM
    cudaFuncSetAttribute(xl_kernel,   cudaFuncAttributeMaxDynamicSharedMemorySize, smXL);
    cudaFuncSetAttribute(uvp_kernel,  cudaFuncAttributeMaxDynamicSharedMemorySize, smUVP);
    cudaFuncSetAttribute(edge_kernel, cudaFuncAttributeMaxDynamicSharedMemorySize, smEDGE);

    prep_kernel<<<40, 256>>>(We, be, W_att, b_att, W_eout, b_eout);
    init_kernel<<<(NN * 128 + 255) / 256, 256>>>();
    xl_kernel<<<148, 256, smXL>>>(x, Wl, bl);
    uvp_kernel<<<dim3(296, 2), 256, smUVP>>>(W_att, W_nout);
    edge_kernel<<<296, 256, smEDGE>>>(edge_attr, edge_index, att, edge_out);
    normalize_kernel<<<(NN * 16 + 255) / 256, 256>>>(node_out, b_nout);
}

// round 12
// speedup vs baseline: 1.2287x; 1.1271x over previous
#include <cuda_runtime.h>
#include <cstdint>

#define NN 50000
#define NE 1600000

typedef unsigned long long u64;

// ---------- scratch (static device globals; no allocation) ----------
__device__ float g_xl[NN * 128];        // [N][H*C]
__device__ float g_uvp[NN * 2 * 192];   // [N][H][u(64)|v(64)|p(64)]
__device__ float g_ex[NE * 2];          // exp(alpha)
__device__ float g_denom[NN * 2];
__device__ float g_Wall[64 * 160];      // [Wcomb_h0 | Wcomb_h1 | Wfold]
__device__ float g_biasAll[160];
__device__ float g_bias192[192];        // [b_att | 0 | 0]

// ---------- f32x2 helpers ----------
__device__ __forceinline__ u64 pack2(float a) {
    u64 d; asm("mov.b64 %0,{%1,%1};" : "=l"(d) : "r"(__float_as_uint(a))); return d;
}
__device__ __forceinline__ u64 ffma2(u64 a, u64 b, u64 c) {
    u64 d; asm("fma.rn.f32x2 %0,%1,%2,%3;" : "=l"(d) : "l"(a), "l"(b), "l"(c)); return d;
}
__device__ __forceinline__ u64 fadd2(u64 a, u64 b) {
    u64 d; asm("add.rn.f32x2 %0,%1,%2;" : "=l"(d) : "l"(a), "l"(b)); return d;
}
__device__ __forceinline__ float2 unpk2(u64 v) {
    float2 r; asm("mov.b64 {%0,%1}, %2;" : "=f"(r.x), "=f"(r.y) : "l"(v)); return r;
}

// ---------- fused weight folding + output init (one launch; moves edge_kernel into ncu's slot) ----------
// Shapes: We (64, 64), W_att (160, 64), W_eout (64, 32), be (64,), b_att (64,), b_eout (32,)
__global__ void prep_init_kernel(float* __restrict__ node_out, const float* __restrict__ b_nout,
                                 const float* __restrict__ We, const float* __restrict__ be,
                                 const float* __restrict__ W_att, const float* __restrict__ b_att,
                                 const float* __restrict__ W_eout, const float* __restrict__ b_eout) {
    int id = blockIdx.x * blockDim.x + threadIdx.x;
    if (id < 64 * 160) {
        int k = id / 160, col = id % 160;
        float acc = 0.f;
        if (col < 128) {                    // attention e-term fold, head h
            int h = col >> 6, j = col & 63;
            #pragma unroll 8
            for (int m = 0; m < 32; m++)
                acc += We[k * 64 + h * 32 + m] * W_att[(128 + m) * 64 + j];
        } else {                            // edge_out fold
            int j = col - 128;
            #pragma unroll 8
            for (int m = 0; m < 64; m++)
                acc += We[k * 64 + m] * W_eout[m * 32 + j];
        }
        g_Wall[id] = acc;
    }
    if (id < 160) {
        float acc = 0.f;
        if (id < 128) {
            int h = id >> 6, j = id & 63;
            for (int m = 0; m < 32; m++)
                acc += be[h * 32 + m] * W_att[(128 + m) * 64 + j];
        } else {
            int j = id - 128;
            for (int m = 0; m < 64; m++)
                acc += be[m] * W_eout[m * 32 + j];
            acc += b_eout[j];
        }
        g_biasAll[id] = acc;
    }
    if (id < 192) g_bias192[id] = (id < 64) ? b_att[id] : 0.f;
    if (id < NN * 64) node_out[id] = b_nout[id & 63];
    if (id < NN * 2) g_denom[id] = 0.f;
}

// ---------- xl = x @ Wl + bl : [50000,128] x [128,128], 128-row tiles, 4 rows/thread ----------
__global__ void __launch_bounds__(256, 1)
xl_kernel(const float* __restrict__ x, const float* __restrict__ Wl,
          const float* __restrict__ bl) {
    extern __shared__ float sm[];
    float* sW = sm;             // 16384
    float* sB = sm + 16384;     // 128
    float* sX = sm + 16512;     // 128*132
    int tid = threadIdx.x, tx = tid & 7, ty = tid >> 3;
    for (int i = tid; i < 16384; i += 256) sW[i] = Wl[i];
    if (tid < 128) sB[tid] = bl[tid];
    for (int t = blockIdx.x; t < (NN + 127) / 128; t += gridDim.x) {
        int r0 = t * 128;
        __syncthreads();
        for (int i = tid; i < 128 * 32; i += 256) {
            int r = i >> 5, kv = i & 31;
            float4 v = (r0 + r < NN) ? *(const float4*)&x[(size_t)(r0 + r) * 128 + kv * 4]
                                     : make_float4(0.f, 0.f, 0.f, 0.f);
            *(float4*)&sX[r * 132 + kv * 4] = v;
        }
        __syncthreads();
        u64 acc[4][8];
        #pragma unroll
        for (int r = 0; r < 4; r++)
            #pragma unroll
            for (int j = 0; j < 8; j++) acc[r][j] = 0ULL;
        #pragma unroll 2
        for (int k = 0; k < 128; k++) {
            u64 a0 = pack2(sX[(ty * 4 + 0) * 132 + k]);
            u64 a1 = pack2(sX[(ty * 4 + 1) * 132 + k]);
            u64 a2 = pack2(sX[(ty * 4 + 2) * 132 + k]);
            u64 a3 = pack2(sX[(ty * 4 + 3) * 132 + k]);
            const ulonglong2* w = (const ulonglong2*)(sW + k * 128);
            #pragma unroll
            for (int j = 0; j < 4; j++) {
                ulonglong2 w2 = w[j * 8 + tx];
                acc[0][2*j] = ffma2(a0, w2.x, acc[0][2*j]); acc[0][2*j+1] = ffma2(a0, w2.y, acc[0][2*j+1]);
                acc[1][2*j] = ffma2(a1, w2.x, acc[1][2*j]); acc[1][2*j+1] = ffma2(a1, w2.y, acc[1][2*j+1]);
                acc[2][2*j] = ffma2(a2, w2.x, acc[2][2*j]); acc[2][2*j+1] = ffma2(a2, w2.y, acc[2][2*j+1]);
                acc[3][2*j] = ffma2(a3, w2.x, acc[3][2*j]); acc[3][2*j+1] = ffma2(a3, w2.y, acc[3][2*j+1]);
            }
        }
        const u64* b2 = (const u64*)sB;
        #pragma unroll
        for (int r = 0; r < 4; r++) {
            int row = r0 + ty * 4 + r;
            if (row < NN) {
                #pragma unroll
                for (int j = 0; j < 4; j++) {
                    u64 vv[2] = { fadd2(acc[r][2*j],   b2[j * 16 + tx * 2]),
                                  fadd2(acc[r][2*j+1], b2[j * 16 + tx * 2 + 1]) };
                    *(float4*)&g_xl[(size_t)row * 128 + j * 32 + tx * 4] = *(float4*)vv;
                }
            }
        }
    }
}

// ---------- [u|v|p](n,h) = xl[n,h] @ [Watt[0:64] | Watt[64:128] | Wnout_h] + [b_att|0|0] ----------
// 96-row tiles, 3 rows/thread, 2 CTAs/SM (confirmed 87.6us, no spill)
__global__ void __launch_bounds__(256, 2)
uvp_kernel(const float* __restrict__ W_att, const float* __restrict__ W_nout) {
    extern __shared__ float sm[];
    float* sW = sm;             // 64*192 = 12288
    float* sB = sm + 12288;     // 192
    float* sX = sm + 12480;     // 96*68 = 6528
    int tid = threadIdx.x, tx = tid & 7, ty = tid >> 3, h = blockIdx.y;
    for (int i = tid; i < 12288; i += 256) {
        int c = i / 192, j = i % 192;
        sW[i] = (j < 128) ? W_att[((j < 64) ? c : 64 + c) * 64 + (j & 63)]
                          : W_nout[(h * 64 + c) * 64 + (j - 128)];
    }
    if (tid < 192) sB[tid] = g_bias192[tid];
    for (int t = blockIdx.x; t < (NN + 95) / 96; t += gridDim.x) {
        int r0 = t * 96;
        __syncthreads();
        for (int i = tid; i < 96 * 16; i += 256) {
            int r = i >> 4, kv = i & 15;
            float4 v = (r0 + r < NN)
                ? *(const float4*)&g_xl[(size_t)(r0 + r) * 128 + h * 64 + kv * 4]
                : make_float4(0.f, 0.f, 0.f, 0.f);
            *(float4*)&sX[r * 68 + kv * 4] = v;
        }
        __syncthreads();
        u64 acc[3][12];
        #pragma unroll
        for (int r = 0; r < 3; r++)
            #pragma unroll
            for (int j = 0; j < 12; j++) acc[r][j] = 0ULL;
        #pragma unroll 2
        for (int k = 0; k < 64; k++) {
            u64 a0 = pack2(sX[(ty * 3 + 0) * 68 + k]);
            u64 a1 = pack2(sX[(ty * 3 + 1) * 68 + k]);
            u64 a2 = pack2(sX[(ty * 3 + 2) * 68 + k]);
            const ulonglong2* w = (const ulonglong2*)(sW + k * 192);
            #pragma unroll
            for (int j = 0; j < 6; j++) {
                ulonglong2 w2 = w[j * 8 + tx];
                acc[0][2*j] = ffma2(a0, w2.x, acc[0][2*j]); acc[0][2*j+1] = ffma2(a0, w2.y, acc[0][2*j+1]);
                acc[1][2*j] = ffma2(a1, w2.x, acc[1][2*j]); acc[1][2*j+1] = ffma2(a1, w2.y, acc[1][2*j+1]);
                acc[2][2*j] = ffma2(a2, w2.x, acc[2][2*j]); acc[2][2*j+1] = ffma2(a2, w2.y, acc[2][2*j+1]);
            }
        }
        const u64* b2 = (const u64*)sB;
        #pragma unroll
        for (int r = 0; r < 3; r++) {
            int n = r0 + ty * 3 + r;
            if (n < NN) {
                #pragma unroll
                for (int j = 0; j < 6; j++) {
                    u64 vv[2] = { fadd2(acc[r][2*j],   b2[j * 16 + tx * 2]),
                                  fadd2(acc[r][2*j+1], b2[j * 16 + tx * 2 + 1]) };
                    *(float4*)&g_uvp[((size_t)n * 2 + h) * 192 + j * 32 + tx * 4] = *(float4*)vv;
                }
            }
        }
    }
}

// ---------- edge: z = ea@Wall + bias (regs); edge_out; alpha via shuffle; denom ----------
// 128-edge tiles, 4 edges/thread, 2 CTAs/SM (R8 config + batched gathers)
__global__ void __launch_bounds__(256, 2)
edge_kernel(const float* __restrict__ ea, const int* __restrict__ ei,
            const float* __restrict__ att, float* __restrict__ eout) {
    extern __shared__ float sm[];
    float* sW  = sm;             // 64*160 = 10240
    float* sB  = sm + 10240;     // 160
    float* sA  = sm + 10400;     // 128
    float* sEA = sm + 10528;     // 128*68 = 8704
    int*   sSD = (int*)(sm + 19232); // 256: [src(128) | dst(128)]
    int tid = threadIdx.x, tx = tid & 7, ty = tid >> 3;
    for (int i = tid; i < 10240; i += 256) sW[i] = g_Wall[i];
    if (tid < 160) sB[tid] = g_biasAll[tid];
    if (tid < 128) sA[tid] = att[tid];
    for (int t = blockIdx.x; t < NE / 128; t += gridDim.x) {
        int e0 = t * 128;
        __syncthreads();        // protect sEA/sSD from previous iteration's readers
        for (int i = tid; i < 128 * 16; i += 256) {
            int r = i >> 4, kv = i & 15;
            *(float4*)&sEA[r * 68 + kv * 4] =
                *(const float4*)&ea[(size_t)(e0 + r) * 64 + kv * 4];
        }
        if (tid < 128) sSD[tid] = ei[e0 + tid];
        else           sSD[tid] = ei[NE + e0 + tid - 128];
        __syncthreads();
        u64 acc[4][10];
        #pragma unroll
        for (int r = 0; r < 4; r++)
            #pragma unroll
            for (int j = 0; j < 10; j++) acc[r][j] = 0ULL;
        #pragma unroll 2
        for (int k = 0; k < 64; k++) {
            u64 a0 = pack2(sEA[(ty * 4 + 0) * 68 + k]);
            u64 a1 = pack2(sEA[(ty * 4 + 1) * 68 + k]);
            u64 a2 = pack2(sEA[(ty * 4 + 2) * 68 + k]);
            u64 a3 = pack2(sEA[(ty * 4 + 3) * 68 + k]);
            const ulonglong2* w = (const ulonglong2*)(sW + k * 160);
            #pragma unroll
            for (int j = 0; j < 5; j++) {
                ulonglong2 w2 = w[j * 8 + tx];
                acc[0][2*j] = ffma2(a0, w2.x, acc[0][2*j]); acc[0][2*j+1] = ffma2(a0, w2.y, acc[0][2*j+1]);
                acc[1][2*j] = ffma2(a1, w2.x, acc[1][2*j]); acc[1][2*j+1] = ffma2(a1, w2.y, acc[1][2*j+1]);
                acc[2][2*j] = ffma2(a2, w2.x, acc[2][2*j]); acc[2][2*j+1] = ffma2(a2, w2.y, acc[2][2*j+1]);
                acc[3][2*j] = ffma2(a3, w2.x, acc[3][2*j]); acc[3][2*j+1] = ffma2(a3, w2.y, acc[3][2*j+1]);
            }
        }
        const u64* b2 = (const u64*)sB;
        #pragma unroll
        for (int r = 0; r < 4; r++) {
            int e = ty * 4 + r, ge = e0 + e;
            int src = sSD[e], dst = sSD[128 + e];
            // edge_out cols (j=4), bias folded
            {
                u64 vv[2] = { fadd2(acc[r][8], b2[4 * 16 + tx * 2]),
                              fadd2(acc[r][9], b2[4 * 16 + tx * 2 + 1]) };
                *(float4*)&eout[(size_t)ge * 32 + tx * 4] = *(float4*)vv;
            }
            // alpha partials over this thread's 8 cols per head (batched gathers per head)
            float p0 = 0.f, p1 = 0.f;
            #pragma unroll
            for (int hh = 0; hh < 2; hh++) {
                const float* gu = &g_uvp[((size_t)dst * 2 + hh) * 192];
                const float* gv = &g_uvp[((size_t)src * 2 + hh) * 192 + 64];
                int lc0 = tx * 4, lc1 = 32 + tx * 4;
                // batch the 4 global gathers before any dependent math
                float4 uu0 = *(const float4*)&gu[lc0];
                float4 uu1 = *(const float4*)&gu[lc1];
                float4 vv0 = *(const float4*)&gv[lc0];
                float4 vv1 = *(const float4*)&gv[lc1];
                int j0 = hh * 2, j1 = hh * 2 + 1;
                float2 zA0 = unpk2(fadd2(acc[r][2*j0],   b2[j0 * 16 + tx * 2]));
                float2 zB0 = unpk2(fadd2(acc[r][2*j0+1], b2[j0 * 16 + tx * 2 + 1]));
                float2 zA1 = unpk2(fadd2(acc[r][2*j1],   b2[j1 * 16 + tx * 2]));
                float2 zB1 = unpk2(fadd2(acc[r][2*j1+1], b2[j1 * 16 + tx * 2 + 1]));
                float4 aa0 = *(const float4*)&sA[hh * 64 + lc0];
                float4 aa1 = *(const float4*)&sA[hh * 64 + lc1];
                float p = 0.f, t0;
                t0 = uu0.x + vv0.x + zA0.x; t0 = t0 > 0.f ? t0 : 0.2f * t0; p = fmaf(t0, aa0.x, p);
                t0 = uu0.y + vv0.y + zA0.y; t0 = t0 > 0.f ? t0 : 0.2f * t0; p = fmaf(t0, aa0.y, p);
                t0 = uu0.z + vv0.z + zB0.x; t0 = t0 > 0.f ? t0 : 0.2f * t0; p = fmaf(t0, aa0.z, p);
                t0 = uu0.w + vv0.w + zB0.y; t0 = t0 > 0.f ? t0 : 0.2f * t0; p = fmaf(t0, aa0.w, p);
                t0 = uu1.x + vv1.x + zA1.x; t0 = t0 > 0.f ? t0 : 0.2f * t0; p = fmaf(t0, aa1.x, p);
                t0 = uu1.y + vv1.y + zA1.y; t0 = t0 > 0.f ? t0 : 0.2f * t0; p = fmaf(t0, aa1.y, p);
                t0 = uu1.z + vv1.z + zB1.x; t0 = t0 > 0.f ? t0 : 0.2f * t0; p = fmaf(t0, aa1.z, p);
                t0 = uu1.w + vv1.w + zB1.y; t0 = t0 > 0.f ? t0 : 0.2f * t0; p = fmaf(t0, aa1.w, p);
                if (hh == 0) p0 = p; else p1 = p;
            }
            // reduce across the 8 tx lanes (lane bits 0-2)
            #pragma unroll
            for (int off = 1; off < 8; off <<= 1) {
                p0 += __shfl_xor_sync(0xFFFFFFFFu, p0, off);
                p1 += __shfl_xor_sync(0xFFFFFFFFu, p1, off);
            }
            if (tx == 0) {
                float ex = __expf(p0);   // softmax shift-invariant; |alpha| small
                g_ex[(size_t)ge * 2] = ex;
                atomicAdd(&g_denom[dst * 2], ex);
            } else if (tx == 1) {
                float ex = __expf(p1);
                g_ex[(size_t)ge * 2 + 1] = ex;
                atomicAdd(&g_denom[dst * 2 + 1], ex);
            }
        }
    }
}

// ---------- node_out[dst] += sum_h (ex_h/denom_h) * p[src,h] ----------
__global__ void scatter_kernel(const int* __restrict__ ei, float* __restrict__ node_out) {
    int gid = blockIdx.x * blockDim.x + threadIdx.x;
    if (gid >= NE * 8) return;
    int e = gid >> 3, part = gid & 7;
    int src = ei[e];
    int dst = ei[NE + e];
    float w0 = g_ex[(size_t)e * 2]     / (g_denom[dst * 2]     + 1e-16f);
    float w1 = g_ex[(size_t)e * 2 + 1] / (g_denom[dst * 2 + 1] + 1e-16f);
    const float4* p0 = (const float4*)&g_uvp[((size_t)src * 2 + 0) * 192 + 128];
    const float4* p1 = (const float4*)&g_uvp[((size_t)src * 2 + 1) * 192 + 128];
    float* ob = node_out + (size_t)dst * 64 + part * 8;
    #pragma unroll
    for (int i = 0; i < 2; i++) {
        float4 a = p0[part * 2 + i];
        float4 b = p1[part * 2 + i];
        float4 s;
        s.x = w0 * a.x + w1 * b.x;
        s.y = w0 * a.y + w1 * b.y;
        s.z = w0 * a.z + w1 * b.z;
        s.w = w0 * a.w + w1 * b.w;
        asm volatile("red.global.add.v4.f32 [%0], {%1,%2,%3,%4};"
                     :: "l"(ob + i * 4), "f"(s.x), "f"(s.y), "f"(s.z), "f"(s.w)
                     : "memory");
    }
}

// ---------- launch ----------
extern "C" void kernel_launch(void* const* d_in, const int* in_sizes, int n_in,
                              void* d_out, int out_size) {
    (void)in_sizes; (void)n_in; (void)out_size;
    const float* x          = (const float*)d_in[0];
    const float* edge_attr  = (const float*)d_in[1];
    const int*   edge_index = (const int*)d_in[2];
    const float* Wl     = (const float*)d_in[3];
    const float* bl     = (const float*)d_in[4];
    const float* We     = (const float*)d_in[5];
    const float* be     = (const float*)d_in[6];
    const float* W_att  = (const float*)d_in[7];
    const float* b_att  = (const float*)d_in[8];
    const float* att    = (const float*)d_in[9];
    const float* W_nout = (const float*)d_in[10];
    const float* b_nout = (const float*)d_in[11];
    const float* W_eout = (const float*)d_in[12];
    const float* b_eout = (const float*)d_in[13];

    float* node_out = (float*)d_out;                   // [50000, 64]
    float* edge_out = node_out + (size_t)NN * 64;      // [1600000, 32]

    const int smXL   = (16384 + 128 + 128 * 132) * 4;      // 133632 -> 1 CTA/SM
    const int smUVP  = (12288 + 192 + 96 * 68) * 4;        //  76032 -> 2 CTAs/SM
    const int smEDGE = (10528 + 128 * 68) * 4 + 256 * 4;   //  77952 -> 2 CTAs/SM
    cudaFuncSetAttribute(xl_kernel,   cudaFuncAttributeMaxDynamicSharedMemorySize, smXL);
    cudaFuncSetAttribute(uvp_kernel,  cudaFuncAttributeMaxDynamicSharedMemorySize, smUVP);
    cudaFuncSetAttribute(edge_kernel, cudaFuncAttributeMaxDynamicSharedMemorySize, smEDGE);

    prep_init_kernel<<<(NN * 64 + 255) / 256, 256>>>(node_out, b_nout,
                                                     We, be, W_att, b_att, W_eout, b_eout);
    xl_kernel<<<148, 256, smXL>>>(x, Wl, bl);
    uvp_kernel<<<dim3(296, 2), 256, smUVP>>>(W_att, W_nout);
    edge_kernel<<<296, 256, smEDGE>>>(edge_attr, edge_index, att, edge_out);
    scatter_kernel<<<(NE * 8 + 255) / 256, 256>>>(edge_index, node_out);
}